// round 11
// baseline (speedup 1.0000x reference)
#include <cuda_runtime.h>

#define N_NODES 100000
#define N_EDGES 1600000
#define HMW 32            // concatenated mu(16) | logstd(16)
#define OUTC 16

#define NB 296            // 148 SMs x 2 resident blocks (guaranteed by launch_bounds)
#define NT 256
#define TOT (NB * NT)     // 75776 threads
#define NLANES (TOT / 4)  // 18944 node-lanes for the dense phase

// ---------------- scratch (device globals; no allocations allowed) -------------
__device__ float g_deg  [N_NODES];         // in-degree count (dst)
__device__ float g_acc0 [N_NODES * 2];     // layer-1 aggregation of dis*x
__device__ float g_gvec [N_NODES * HMW];   // g = dis * (h @ [Wmu|Wls])
__device__ float g_acc1 [N_NODES * HMW];   // layer-2 accumulator (seeded = gvec)
__device__ int   g_src32[N_EDGES];         // compacted int32 src (int64 input only)
__device__ int   g_dst32[N_EDGES];         // compacted int32 dst (int64 input only)
__device__ int   g_is64;                   // edge_index dtype flag
__device__ unsigned long long g_bar[8];    // monotonic barrier tickets (never reset)

// ---------------- vectorized L2 reductions (sm_90+) -----------------------------
__device__ __forceinline__ void red_add_v4(float* addr, float4 v) {
    asm volatile("red.global.add.v4.f32 [%0], {%1, %2, %3, %4};"
                 :: "l"(addr), "f"(v.x), "f"(v.y), "f"(v.z), "f"(v.w) : "memory");
}
__device__ __forceinline__ void red_add_v2(float* addr, float a, float b) {
    asm volatile("red.global.add.v2.f32 [%0], {%1, %2};"
                 :: "l"(addr), "f"(a), "f"(b) : "memory");
}

// ---------------- software grid barrier (graph-replay safe) ----------------------
// Monotonic ticket counter: each launch adds exactly NB per phase, so a block's
// release target is (ticket/NB + 1)*NB. No resets -> no reset races across
// graph replays. threadfence = release; acquire-load = acquire.
__device__ __forceinline__ void gbar(int p) {
    __syncthreads();
    if (threadIdx.x == 0) {
        __threadfence();
        unsigned long long t = atomicAdd(&g_bar[p], 1ULL);
        unsigned long long target = (t / NB + 1ULL) * (unsigned long long)NB;
        unsigned long long v;
        do {
            asm volatile("ld.acquire.gpu.b64 %0, [%1];"
                         : "=l"(v) : "l"(&g_bar[p]) : "memory");
        } while (v < target);
    }
    __syncthreads();
}

// ================= single persistent kernel: all 6 phases =======================
__global__ void __launch_bounds__(NT, 2) k_fused(
        const float* __restrict__ x, const void* __restrict__ ei,
        const float* __restrict__ W1, const float* __restrict__ b1,
        const float* __restrict__ Wmu, const float* __restrict__ bmu,
        const float* __restrict__ Wls, const float* __restrict__ bls,
        float* __restrict__ out) {
    __shared__ float4 sW4[64][8];   // [k][j/4] of concatenated [Wmu|Wls], 8KB
    __shared__ float4 sWb[64];      // (W1[0][k], W1[1][k], b1[k], 0)
    __shared__ unsigned s_or[NT];

    const int t = threadIdx.x;
    const int gtid = blockIdx.x * NT + t;

    // ---------- phase 0: dtype detect (block 0) + zero deg/acc0 + stage weights --
    if (blockIdx.x == 0) {
        unsigned v = 0;
        for (int i = t; i < 4096; i += NT)
            v |= ((const unsigned*)ei)[2 * i + 1];
        s_or[t] = v;
        __syncthreads();
        for (int s = NT / 2; s > 0; s >>= 1) {
            if (t < s) s_or[t] |= s_or[t + s];
            __syncthreads();
        }
        if (t == 0) g_is64 = (s_or[0] == 0u) ? 1 : 0;
    }
    {
        const float4 z = make_float4(0.f, 0.f, 0.f, 0.f);
        if (gtid < N_NODES * 2 / 4) ((float4*)g_acc0)[gtid] = z;
        if (gtid < N_NODES / 4)     ((float4*)g_deg )[gtid] = z;
    }
    for (int i = t; i < 512; i += NT) {     // stage weights (smem persists)
        int k = i >> 3, q = i & 7;
        sW4[k][q] = (q < 4) ? ((const float4*)Wmu)[k * 4 + q]
                            : ((const float4*)Wls)[k * 4 + (q - 4)];
    }
    if (t < 64) sWb[t] = make_float4(W1[t], W1[64 + t], b1[t], 0.0f);
    gbar(0);

    const int is64 = g_is64;
    const int* srcp = is64 ? g_src32 : (const int*)ei;
    const int* dstp = is64 ? g_dst32 : ((const int*)ei) + N_EDGES;

    // ---------- phase 1: degree (+ compaction only if int64 input) ---------------
    if (is64) {
        const long long* p = (const long long*)ei;
        for (int e = gtid; e < N_EDGES; e += TOT) {
            int src = (int)p[e];
            int dst = (int)p[N_EDGES + e];
            g_src32[e] = src;
            g_dst32[e] = dst;
            atomicAdd(&g_deg[dst], 1.0f);
        }
    } else {
        for (int e = gtid; e < N_EDGES; e += TOT)
            atomicAdd(&g_deg[dstp[e]], 1.0f);
    }
    gbar(1);

    // ---------- phase 2: layer-1 scatter acc0[dst] += dis[src]*x[src] ------------
    for (int e = gtid; e < N_EDGES; e += TOT) {
        int src = srcp[e];
        int dst = dstp[e];
        float ds = rsqrtf(1.0f + g_deg[src]);
        float2 xv = ((const float2*)x)[src];
        red_add_v2(&g_acc0[2 * dst], ds * xv.x, ds * xv.y);
    }
    gbar(2);

    // ---------- phase 3: dense (R6-proven shape: 4 thr/node x 4 nodes/thread) ----
    {
        const int part = t & 3;
        const int lnode = gtid >> 2;          // 0..NLANES-1
        const int q0 = part * 2;
        for (int base = 0; base < N_NODES; base += TOT) {   // 4*NLANES nodes/sweep
            float a0[4], a1[4], dd[4];
            #pragma unroll
            for (int i = 0; i < 4; i++) {
                int n = base + lnode + NLANES * i;
                int nc = (n < N_NODES) ? n : 0;
                float d = rsqrtf(1.0f + g_deg[nc]);
                float2 xv = ((const float2*)x)[nc];
                float2 av = ((const float2*)g_acc0)[nc];
                a0[i] = d * av.x + d * d * xv.x;
                a1[i] = d * av.y + d * d * xv.y;
                dd[i] = d;
            }
            float acc[4][8];
            #pragma unroll
            for (int i = 0; i < 4; i++)
                #pragma unroll
                for (int j = 0; j < 8; j++) acc[i][j] = 0.0f;

            #pragma unroll 4
            for (int k = 0; k < 64; k++) {
                float4 wb = sWb[k];
                float4 wA = sW4[k][q0];
                float4 wB = sW4[k][q0 + 1];
                #pragma unroll
                for (int i = 0; i < 4; i++) {
                    float hk = fmaxf(0.0f, fmaf(a0[i], wb.x, fmaf(a1[i], wb.y, wb.z)));
                    acc[i][0] = fmaf(hk, wA.x, acc[i][0]);
                    acc[i][1] = fmaf(hk, wA.y, acc[i][1]);
                    acc[i][2] = fmaf(hk, wA.z, acc[i][2]);
                    acc[i][3] = fmaf(hk, wA.w, acc[i][3]);
                    acc[i][4] = fmaf(hk, wB.x, acc[i][4]);
                    acc[i][5] = fmaf(hk, wB.y, acc[i][5]);
                    acc[i][6] = fmaf(hk, wB.z, acc[i][6]);
                    acc[i][7] = fmaf(hk, wB.w, acc[i][7]);
                }
            }
            #pragma unroll
            for (int i = 0; i < 4; i++) {
                int n = base + lnode + NLANES * i;
                if (n < N_NODES) {
                    float4 vA = make_float4(dd[i] * acc[i][0], dd[i] * acc[i][1],
                                            dd[i] * acc[i][2], dd[i] * acc[i][3]);
                    float4 vB = make_float4(dd[i] * acc[i][4], dd[i] * acc[i][5],
                                            dd[i] * acc[i][6], dd[i] * acc[i][7]);
                    float4* gout = (float4*)(g_gvec + n * HMW + part * 8);
                    float4* aout = (float4*)(g_acc1 + n * HMW + part * 8);
                    gout[0] = vA; gout[1] = vB;
                    aout[0] = vA; aout[1] = vB;   // self-loop seed (no zeroing pass)
                }
            }
        }
    }
    gbar(3);

    // ---------- phase 4: layer-2 scatter acc1[dst][:] += gvec[src][:] ------------
    {
        const int total = N_EDGES * 8;
        #pragma unroll 4
        for (int idx = gtid; idx < total; idx += TOT) {
            int e = idx >> 3, q = idx & 7;
            int src = srcp[e];
            int dst = dstp[e];
            float4 v = ((const float4*)g_gvec)[src * 8 + q];
            red_add_v4(&g_acc1[dst * HMW + q * 4], v);
        }
    }
    gbar(4);

    // ---------- phase 5: epilogue out = dis*acc1 + bias --------------------------
    for (int idx = gtid; idx < N_NODES * 8; idx += TOT) {
        int n = idx >> 3, q = idx & 7;
        float d = rsqrtf(1.0f + g_deg[n]);
        float4 a = ((const float4*)g_acc1)[idx];
        float4 b = (q < 4) ? ((const float4*)bmu)[q] : ((const float4*)bls)[q - 4];
        float4 v = make_float4(fmaf(d, a.x, b.x), fmaf(d, a.y, b.y),
                               fmaf(d, a.z, b.z), fmaf(d, a.w, b.w));
        float* dst = (q < 4) ? out + n * OUTC + q * 4
                             : out + N_NODES * OUTC + n * OUTC + (q - 4) * 4;
        *(float4*)dst = v;
    }
}

extern "C" void kernel_launch(void* const* d_in, const int* in_sizes, int n_in,
                              void* d_out, int out_size) {
    const float* x    = (const float*)d_in[0];
    const void*  ei   = d_in[1];                 // int32 or int64, detected on device
    const float* W1   = (const float*)d_in[2];
    const float* b1   = (const float*)d_in[3];
    const float* Wmu  = (const float*)d_in[4];
    const float* bmu  = (const float*)d_in[5];
    const float* Wls  = (const float*)d_in[6];
    const float* bls  = (const float*)d_in[7];
    float* out = (float*)d_out;

    k_fused<<<NB, NT>>>(x, ei, W1, b1, Wmu, bmu, Wls, bls, out);
}

// round 12
// speedup vs baseline: 1.1935x; 1.1935x over previous
#include <cuda_runtime.h>
#include <cuda_fp16.h>

#define N_NODES 100000
#define N_EDGES 1600000
#define HMW 32            // concatenated mu(16) | logstd(16)
#define OUTC 16

// ---------------- scratch (device globals; no allocations allowed) -------------
__device__ float  g_deg  [N_NODES];         // in-degree count (dst)
__device__ float  g_acc0 [N_NODES * 2];     // layer-1 aggregation of dis*x
__device__ __half g_gvech[N_NODES * HMW];   // g = dis*(h@[Wmu|Wls]) in fp16 (gather payload)
__device__ float  g_acc1 [N_NODES * HMW];   // layer-2 accumulator (seeded = gvec, f32 exact)
__device__ int    g_src32[N_EDGES];         // compacted int32 src
__device__ int    g_dst32[N_EDGES];         // compacted int32 dst
__device__ int    g_is64;                   // edge_index dtype flag

// ---------------- vectorized L2 reductions (sm_90+) -----------------------------
__device__ __forceinline__ void red_add_v4(float* addr, float4 v) {
    asm volatile("red.global.add.v4.f32 [%0], {%1, %2, %3, %4};"
                 :: "l"(addr), "f"(v.x), "f"(v.y), "f"(v.z), "f"(v.w) : "memory");
}
__device__ __forceinline__ void red_add_v2(float* addr, float a, float b) {
    asm volatile("red.global.add.v2.f32 [%0], {%1, %2};"
                 :: "l"(addr), "f"(a), "f"(b) : "memory");
}

// ---------------- init: block 0 detects dtype; all blocks zero deg + acc0 -------
// int64 indices < 100000 have all-zero high words -> OR over 4096 words detects.
__global__ void k_init(const unsigned* ei_words) {
    if (blockIdx.x == 0) {
        __shared__ unsigned s_or[256];
        unsigned v = 0;
        for (int i = threadIdx.x; i < 4096; i += 256)
            v |= ei_words[2 * i + 1];
        s_or[threadIdx.x] = v;
        __syncthreads();
        for (int s = 128; s > 0; s >>= 1) {
            if (threadIdx.x < s) s_or[threadIdx.x] |= s_or[threadIdx.x + s];
            __syncthreads();
        }
        if (threadIdx.x == 0) g_is64 = (s_or[0] == 0u) ? 1 : 0;
    }
    const float4 z = make_float4(0.f, 0.f, 0.f, 0.f);
    int i = blockIdx.x * 256 + threadIdx.x;
    if (i < N_NODES * 2 / 4) ((float4*)g_acc0)[i] = z;   // 50000 float4
    if (i < N_NODES / 4)     ((float4*)g_deg )[i] = z;   // 25000 float4
}

// ---------------- degree + edge compaction to int32 -----------------------------
__global__ void k_deg(const void* ei) {
    int e = blockIdx.x * 256 + threadIdx.x;
    if (e >= N_EDGES) return;
    int src, dst;
    if (g_is64) {
        const long long* p = (const long long*)ei;
        src = (int)p[e];
        dst = (int)p[N_EDGES + e];
    } else {
        const int* p = (const int*)ei;
        src = p[e];
        dst = p[N_EDGES + e];
    }
    g_src32[e] = src;
    g_dst32[e] = dst;
    atomicAdd(&g_deg[dst], 1.0f);
}

// ---------------- layer-1 scatter: acc0[dst] += dis[src] * x[src]  (2 feats) ----
__global__ void k_scatter0(const float* __restrict__ x) {
    int e = blockIdx.x * 256 + threadIdx.x;
    if (e >= N_EDGES) return;
    int src = g_src32[e];
    int dst = g_dst32[e];
    float ds = rsqrtf(1.0f + g_deg[src]);
    float2 xv = ((const float2*)x)[src];
    red_add_v2(&g_acc0[2 * dst], ds * xv.x, ds * xv.y);
}

// ---------------- dense: h = relu(aggX @ W1 + b1); g = dis * (h @ [Wmu|Wls]) ----
// 4 threads/node (8 outputs each) x 4 nodes/thread (R6/R8-proven shape).
// Writes gvec in fp16 (halves the scatter1 gather payload) and seeds acc1 with
// the EXACT f32 self-loop term from registers (replaces the zeroing pass).
__global__ void __launch_bounds__(256) k_hidden(
        const float* __restrict__ x, const float* __restrict__ W1,
        const float* __restrict__ b1,
        const float* __restrict__ Wmu, const float* __restrict__ Wls) {
    __shared__ float4 sW4[64][8];   // [k][j/4] of concatenated [Wmu|Wls], 4KB
    __shared__ float4 sWb[64];      // (W1[0][k], W1[1][k], b1[k], 0)

    int t = threadIdx.x;
    for (int i = t; i < 512; i += 256) {
        int k = i >> 3, q = i & 7;
        sW4[k][q] = (q < 4) ? ((const float4*)Wmu)[k * 4 + q]
                            : ((const float4*)Wls)[k * 4 + (q - 4)];
    }
    if (t < 64) sWb[t] = make_float4(W1[t], W1[64 + t], b1[t], 0.0f);
    __syncthreads();

    int part = t & 3;               // which 8 of the 32 outputs
    int u    = t >> 2;              // 0..63
    int base = blockIdx.x * 256;

    float a0[4], a1[4], dd[4];
    #pragma unroll
    for (int i = 0; i < 4; i++) {
        int n = base + u + 64 * i;
        int nc = (n < N_NODES) ? n : 0;
        float d = rsqrtf(1.0f + g_deg[nc]);
        float2 xv = ((const float2*)x)[nc];
        float2 av = ((const float2*)g_acc0)[nc];
        a0[i] = d * av.x + d * d * xv.x;
        a1[i] = d * av.y + d * d * xv.y;
        dd[i] = d;
    }

    float acc[4][8];
    #pragma unroll
    for (int i = 0; i < 4; i++)
        #pragma unroll
        for (int j = 0; j < 8; j++) acc[i][j] = 0.0f;

    int q0 = part * 2;
    #pragma unroll 4
    for (int k = 0; k < 64; k++) {
        float4 wb = sWb[k];
        float4 wA = sW4[k][q0];
        float4 wB = sW4[k][q0 + 1];
        #pragma unroll
        for (int i = 0; i < 4; i++) {
            float hk = fmaxf(0.0f, fmaf(a0[i], wb.x, fmaf(a1[i], wb.y, wb.z)));
            acc[i][0] = fmaf(hk, wA.x, acc[i][0]);
            acc[i][1] = fmaf(hk, wA.y, acc[i][1]);
            acc[i][2] = fmaf(hk, wA.z, acc[i][2]);
            acc[i][3] = fmaf(hk, wA.w, acc[i][3]);
            acc[i][4] = fmaf(hk, wB.x, acc[i][4]);
            acc[i][5] = fmaf(hk, wB.y, acc[i][5]);
            acc[i][6] = fmaf(hk, wB.z, acc[i][6]);
            acc[i][7] = fmaf(hk, wB.w, acc[i][7]);
        }
    }

    #pragma unroll
    for (int i = 0; i < 4; i++) {
        int n = base + u + 64 * i;
        if (n < N_NODES) {
            float4 vA = make_float4(dd[i] * acc[i][0], dd[i] * acc[i][1],
                                    dd[i] * acc[i][2], dd[i] * acc[i][3]);
            float4 vB = make_float4(dd[i] * acc[i][4], dd[i] * acc[i][5],
                                    dd[i] * acc[i][6], dd[i] * acc[i][7]);
            // exact f32 self-loop seed
            float4* aout = (float4*)(g_acc1 + n * HMW + part * 8);
            aout[0] = vA;
            aout[1] = vB;
            // fp16 gather payload: 8 halves = 16B = one uint4 store
            __half2 h0 = __float22half2_rn(make_float2(vA.x, vA.y));
            __half2 h1 = __float22half2_rn(make_float2(vA.z, vA.w));
            __half2 h2 = __float22half2_rn(make_float2(vB.x, vB.y));
            __half2 h3 = __float22half2_rn(make_float2(vB.z, vB.w));
            uint4 pk;
            pk.x = *(unsigned*)&h0; pk.y = *(unsigned*)&h1;
            pk.z = *(unsigned*)&h2; pk.w = *(unsigned*)&h3;
            *(uint4*)(g_gvech + n * HMW + part * 8) = pk;
        }
    }
}

// ---------------- layer-2 scatter: acc1[dst][:] += gvec_h[src][:]  (32 feats) ---
// 8 threads per edge; each gathers 8B (4 halves), converts to f32, one red.v4.
// Gather payload halved vs f32 (64B/edge); REDG accumulation stays exact f32.
__global__ void k_scatter1() {
    long long tid = (long long)blockIdx.x * 256 + threadIdx.x;
    if (tid >= (long long)N_EDGES * 8) return;
    int e = (int)(tid >> 3), q = (int)(tid & 7);
    int src = g_src32[e];
    int dst = g_dst32[e];
    uint2 w = ((const uint2*)g_gvech)[src * 8 + q];     // 4 halves
    float2 f0 = __half22float2(*(__half2*)&w.x);
    float2 f1 = __half22float2(*(__half2*)&w.y);
    red_add_v4(&g_acc1[dst * HMW + q * 4], make_float4(f0.x, f0.y, f1.x, f1.y));
}

// ---------------- epilogue: out = dis*acc1 + bias; split mu / logstd ------------
__global__ void k_out(const float* __restrict__ bmu, const float* __restrict__ bls,
                      float* __restrict__ out) {
    int tid = blockIdx.x * 256 + threadIdx.x;       // over N_NODES * 8 float4s
    if (tid >= N_NODES * 8) return;
    int n = tid >> 3, q = tid & 7;
    float d = rsqrtf(1.0f + g_deg[n]);
    float4 a = ((const float4*)g_acc1)[tid];
    float4 b = (q < 4) ? ((const float4*)bmu)[q] : ((const float4*)bls)[q - 4];
    float4 v = make_float4(fmaf(d, a.x, b.x), fmaf(d, a.y, b.y),
                           fmaf(d, a.z, b.z), fmaf(d, a.w, b.w));
    float* dst = (q < 4) ? out + n * OUTC + q * 4
                         : out + N_NODES * OUTC + n * OUTC + (q - 4) * 4;
    *(float4*)dst = v;
}

extern "C" void kernel_launch(void* const* d_in, const int* in_sizes, int n_in,
                              void* d_out, int out_size) {
    const float* x    = (const float*)d_in[0];
    const void*  ei   = d_in[1];                 // int32 or int64, detected on device
    const float* W1   = (const float*)d_in[2];
    const float* b1   = (const float*)d_in[3];
    const float* Wmu  = (const float*)d_in[4];
    const float* bmu  = (const float*)d_in[5];
    const float* Wls  = (const float*)d_in[6];
    const float* bls  = (const float*)d_in[7];
    float* out = (float*)d_out;

    const int IB  = (N_NODES * 2 / 4 + 255) / 256;        // 196
    const int EB  = (N_EDGES + 255) / 256;                // 6250
    const int HB  = (N_NODES + 255) / 256;                // 391
    const int OB  = (N_NODES * 8 + 255) / 256;            // 3125
    const int S1B = (int)(((long long)N_EDGES * 8 + 255) / 256);  // 50000

    k_init<<<IB, 256>>>((const unsigned*)ei);
    k_deg<<<EB, 256>>>(ei);
    k_scatter0<<<EB, 256>>>(x);
    k_hidden<<<HB, 256>>>(x, W1, b1, Wmu, Wls);
    k_scatter1<<<S1B, 256>>>();
    k_out<<<OB, 256>>>(bmu, bls, out);
}

// round 13
// speedup vs baseline: 1.2467x; 1.0446x over previous
#include <cuda_runtime.h>
#include <cuda_fp16.h>

#define N_NODES 100000
#define N_EDGES 1600000
#define HMW 32            // concatenated mu(16) | logstd(16)
#define OUTC 16

// ---------------- scratch (device globals; zero at module load) ------------------
// deg/acc0 are ACCUMULATORS: zeroed at the tail of k_scatter1 each launch, so
// every launch (first included) starts from zero. gvech/acc1/dis are fully
// overwritten each launch and need no zeroing.
__device__ float  g_deg  [N_NODES];         // in-degree count (dst)
__device__ float  g_acc0 [N_NODES * 2];     // layer-1 aggregation of dis*x
__device__ float  g_dis  [N_NODES];         // rsqrt(1+deg), written by k_hidden
__device__ __half g_gvech[N_NODES * HMW];   // gvec fp16 (scatter1 gather payload)
__device__ float  g_acc1 [N_NODES * HMW];   // layer-2 accumulator (seed = gvec f32)
__device__ int    g_src32[N_EDGES];         // compacted src (int64 input only)
__device__ int    g_dst32[N_EDGES];         // compacted dst (int64 input only)
__device__ int    g_is64;                   // dtype flag (written by k_deg)

// ---------------- vectorized L2 reductions (sm_90+) -----------------------------
__device__ __forceinline__ void red_add_v4(float* addr, float4 v) {
    asm volatile("red.global.add.v4.f32 [%0], {%1, %2, %3, %4};"
                 :: "l"(addr), "f"(v.x), "f"(v.y), "f"(v.z), "f"(v.w) : "memory");
}
__device__ __forceinline__ void red_add_v2(float* addr, float a, float b) {
    asm volatile("red.global.add.v2.f32 [%0], {%1, %2};"
                 :: "l"(addr), "f"(a), "f"(b) : "memory");
}

// ---------------- degree + per-block dtype detect (+ compaction iff int64) -------
// Detect: sample 256 odd-indexed words. int64 indices < 100000 have zero high
// words; int32 data puts edge values there (P(all 256 == 0) ~ 1e-1280).
__global__ void k_deg(const void* ei) {
    __shared__ unsigned s_or[256];
    int t = threadIdx.x;
    s_or[t] = ((const unsigned*)ei)[2 * t + 1];
    __syncthreads();
    for (int s = 128; s > 0; s >>= 1) {
        if (t < s) s_or[t] |= s_or[t + s];
        __syncthreads();
    }
    int is64 = (s_or[0] == 0u) ? 1 : 0;
    if (blockIdx.x == 0 && t == 0) g_is64 = is64;   // for later kernels

    int e = blockIdx.x * 256 + t;
    if (e >= N_EDGES) return;
    if (is64) {
        const long long* p = (const long long*)ei;
        int src = (int)p[e];
        int dst = (int)p[N_EDGES + e];
        g_src32[e] = src;
        g_dst32[e] = dst;
        atomicAdd(&g_deg[dst], 1.0f);
    } else {
        atomicAdd(&g_deg[((const int*)ei)[N_EDGES + e]], 1.0f);
    }
}

__device__ __forceinline__ void load_edge(const void* ei, int is64, int e,
                                          int& src, int& dst) {
    if (is64) { src = g_src32[e]; dst = g_dst32[e]; }
    else {
        const int* p = (const int*)ei;
        src = p[e];
        dst = p[N_EDGES + e];
    }
}

// ---------------- layer-1 scatter: acc0[dst] += dis[src] * x[src]  (2 feats) ----
__global__ void k_scatter0(const void* ei, const float* __restrict__ x) {
    int e = blockIdx.x * 256 + threadIdx.x;
    if (e >= N_EDGES) return;
    int src, dst;
    load_edge(ei, g_is64, e, src, dst);
    float ds = rsqrtf(1.0f + g_deg[src]);
    float2 xv = ((const float2*)x)[src];
    red_add_v2(&g_acc0[2 * dst], ds * xv.x, ds * xv.y);
}

// ---------------- dense: h = relu(aggX @ W1 + b1); g = dis * (h @ [Wmu|Wls]) ----
// 4 threads/node (8 outputs each) x 4 nodes/thread (R6/R8-proven shape).
// Writes gvec fp16 (gather payload), seeds acc1 with exact f32 self-loop term,
// and part-0 lanes persist g_dis for the epilogue.
__global__ void __launch_bounds__(256) k_hidden(
        const float* __restrict__ x, const float* __restrict__ W1,
        const float* __restrict__ b1,
        const float* __restrict__ Wmu, const float* __restrict__ Wls) {
    __shared__ float4 sW4[64][8];   // [k][j/4] of concatenated [Wmu|Wls]
    __shared__ float4 sWb[64];      // (W1[0][k], W1[1][k], b1[k], 0)

    int t = threadIdx.x;
    for (int i = t; i < 512; i += 256) {
        int k = i >> 3, q = i & 7;
        sW4[k][q] = (q < 4) ? ((const float4*)Wmu)[k * 4 + q]
                            : ((const float4*)Wls)[k * 4 + (q - 4)];
    }
    if (t < 64) sWb[t] = make_float4(W1[t], W1[64 + t], b1[t], 0.0f);
    __syncthreads();

    int part = t & 3;               // which 8 of the 32 outputs
    int u    = t >> 2;              // 0..63
    int base = blockIdx.x * 256;

    float a0[4], a1[4], dd[4];
    #pragma unroll
    for (int i = 0; i < 4; i++) {
        int n = base + u + 64 * i;
        int nc = (n < N_NODES) ? n : 0;
        float d = rsqrtf(1.0f + g_deg[nc]);
        float2 xv = ((const float2*)x)[nc];
        float2 av = ((const float2*)g_acc0)[nc];
        a0[i] = d * av.x + d * d * xv.x;
        a1[i] = d * av.y + d * d * xv.y;
        dd[i] = d;
    }

    float acc[4][8];
    #pragma unroll
    for (int i = 0; i < 4; i++)
        #pragma unroll
        for (int j = 0; j < 8; j++) acc[i][j] = 0.0f;

    int q0 = part * 2;
    #pragma unroll 4
    for (int k = 0; k < 64; k++) {
        float4 wb = sWb[k];
        float4 wA = sW4[k][q0];
        float4 wB = sW4[k][q0 + 1];
        #pragma unroll
        for (int i = 0; i < 4; i++) {
            float hk = fmaxf(0.0f, fmaf(a0[i], wb.x, fmaf(a1[i], wb.y, wb.z)));
            acc[i][0] = fmaf(hk, wA.x, acc[i][0]);
            acc[i][1] = fmaf(hk, wA.y, acc[i][1]);
            acc[i][2] = fmaf(hk, wA.z, acc[i][2]);
            acc[i][3] = fmaf(hk, wA.w, acc[i][3]);
            acc[i][4] = fmaf(hk, wB.x, acc[i][4]);
            acc[i][5] = fmaf(hk, wB.y, acc[i][5]);
            acc[i][6] = fmaf(hk, wB.z, acc[i][6]);
            acc[i][7] = fmaf(hk, wB.w, acc[i][7]);
        }
    }

    #pragma unroll
    for (int i = 0; i < 4; i++) {
        int n = base + u + 64 * i;
        if (n < N_NODES) {
            float4 vA = make_float4(dd[i] * acc[i][0], dd[i] * acc[i][1],
                                    dd[i] * acc[i][2], dd[i] * acc[i][3]);
            float4 vB = make_float4(dd[i] * acc[i][4], dd[i] * acc[i][5],
                                    dd[i] * acc[i][6], dd[i] * acc[i][7]);
            float4* aout = (float4*)(g_acc1 + n * HMW + part * 8);
            aout[0] = vA;                  // exact f32 self-loop seed
            aout[1] = vB;
            __half2 h0 = __float22half2_rn(make_float2(vA.x, vA.y));
            __half2 h1 = __float22half2_rn(make_float2(vA.z, vA.w));
            __half2 h2 = __float22half2_rn(make_float2(vB.x, vB.y));
            __half2 h3 = __float22half2_rn(make_float2(vB.z, vB.w));
            uint4 pk;
            pk.x = *(unsigned*)&h0; pk.y = *(unsigned*)&h1;
            pk.z = *(unsigned*)&h2; pk.w = *(unsigned*)&h3;
            *(uint4*)(g_gvech + n * HMW + part * 8) = pk;
            if (part == 0) g_dis[n] = dd[i];   // persist for epilogue
        }
    }
}

// ---------------- layer-2 scatter + accumulator re-zeroing -----------------------
// Edge range: 8 threads/edge, gather 4 halves -> f32 -> one red.v4 (exact f32
// accumulation). Tail range: zero deg + acc0 for the NEXT launch (they were
// last read by k_hidden; module-load state is already zero for launch #1).
#define S1_EDGE_T (N_EDGES * 8)
#define S1_ZD     (N_NODES / 4)          // deg float4s   (25000)
#define S1_ZA     (N_NODES * 2 / 4)      // acc0 float4s  (50000)
#define S1_TOTAL  (S1_EDGE_T + S1_ZD + S1_ZA)
__global__ void k_scatter1(const void* ei) {
    int tid = blockIdx.x * 256 + threadIdx.x;
    if (tid < S1_EDGE_T) {
        int e = tid >> 3, q = tid & 7;
        int src, dst;
        load_edge(ei, g_is64, e, src, dst);
        uint2 w = ((const uint2*)g_gvech)[src * 8 + q];     // 4 halves
        float2 f0 = __half22float2(*(__half2*)&w.x);
        float2 f1 = __half22float2(*(__half2*)&w.y);
        red_add_v4(&g_acc1[dst * HMW + q * 4], make_float4(f0.x, f0.y, f1.x, f1.y));
    } else {
        int z = tid - S1_EDGE_T;
        const float4 zero = make_float4(0.f, 0.f, 0.f, 0.f);
        if (z < S1_ZD)                ((float4*)g_deg )[z] = zero;
        else if (z < S1_ZD + S1_ZA)   ((float4*)g_acc0)[z - S1_ZD] = zero;
    }
}

// ---------------- epilogue: out = dis*acc1 + bias; split mu / logstd ------------
__global__ void k_out(const float* __restrict__ bmu, const float* __restrict__ bls,
                      float* __restrict__ out) {
    int tid = blockIdx.x * 256 + threadIdx.x;       // over N_NODES * 8 float4s
    if (tid >= N_NODES * 8) return;
    int n = tid >> 3, q = tid & 7;
    float d = g_dis[n];
    float4 a = ((const float4*)g_acc1)[tid];
    float4 b = (q < 4) ? ((const float4*)bmu)[q] : ((const float4*)bls)[q - 4];
    float4 v = make_float4(fmaf(d, a.x, b.x), fmaf(d, a.y, b.y),
                           fmaf(d, a.z, b.z), fmaf(d, a.w, b.w));
    float* dst = (q < 4) ? out + n * OUTC + q * 4
                         : out + N_NODES * OUTC + n * OUTC + (q - 4) * 4;
    *(float4*)dst = v;
}

extern "C" void kernel_launch(void* const* d_in, const int* in_sizes, int n_in,
                              void* d_out, int out_size) {
    const float* x    = (const float*)d_in[0];
    const void*  ei   = d_in[1];                 // int32 or int64, detected on device
    const float* W1   = (const float*)d_in[2];
    const float* b1   = (const float*)d_in[3];
    const float* Wmu  = (const float*)d_in[4];
    const float* bmu  = (const float*)d_in[5];
    const float* Wls  = (const float*)d_in[6];
    const float* bls  = (const float*)d_in[7];
    float* out = (float*)d_out;

    const int EB  = (N_EDGES + 255) / 256;                // 6250
    const int HB  = (N_NODES + 255) / 256;                // 391
    const int OB  = (N_NODES * 8 + 255) / 256;            // 3125
    const int S1B = (S1_TOTAL + 255) / 256;               // 50293

    k_deg<<<EB, 256>>>(ei);
    k_scatter0<<<EB, 256>>>(ei, x);
    k_hidden<<<HB, 256>>>(x, W1, b1, Wmu, Wls);
    k_scatter1<<<S1B, 256>>>(ei);
    k_out<<<OB, 256>>>(bmu, bls, out);
}

// round 14
// speedup vs baseline: 1.4352x; 1.1512x over previous
#include <cuda_runtime.h>
#include <cuda_fp16.h>

#define N_NODES 100000
#define N_EDGES 1600000
#define HMW 32            // concatenated mu(16) | logstd(16)
#define OUTC 16

// ---------------- scratch (device globals; zero at module load) ------------------
// deg/acc0 zeroed at tail of k_scatter1 (last read by k_hidden); acc1h zeroed at
// tail of k_deg (read by k_out AFTER scatter1, so zeroing must be early in the
// launch). Module-load zero state covers the first launch for all of them.
__device__ float  g_deg  [N_NODES];         // in-degree count (dst)
__device__ float  g_acc0 [N_NODES * 2];     // layer-1 aggregation of dis*x
__device__ float  g_dis  [N_NODES];         // rsqrt(1+deg), written by k_hidden
__device__ __half g_gvech[N_NODES * HMW];   // gvec fp16 (gather payload + REDG operand)
__device__ float  g_gself[N_NODES * HMW];   // gvec f32 exact (self-loop term)
__device__ __half g_acc1h[N_NODES * HMW];   // fp16 neighbor accumulator (REDG f16x2)
__device__ int    g_src32[N_EDGES];         // compacted src (int64 input only)
__device__ int    g_dst32[N_EDGES];         // compacted dst (int64 input only)
__device__ int    g_is64;                   // dtype flag (written by k_deg)

// ---------------- vectorized L2 reductions (sm_90+) -----------------------------
__device__ __forceinline__ void red_add_v2(float* addr, float a, float b) {
    asm volatile("red.global.add.v2.f32 [%0], {%1, %2};"
                 :: "l"(addr), "f"(a), "f"(b) : "memory");
}
// 8 packed halves (4 x f16x2) in one 16B reduction lane
__device__ __forceinline__ void red_add_v4h2(__half* addr, uint4 w) {
    asm volatile("red.global.add.noftz.v4.f16x2 [%0], {%1, %2, %3, %4};"
                 :: "l"(addr), "r"(w.x), "r"(w.y), "r"(w.z), "r"(w.w) : "memory");
}

// ---------------- degree + dtype detect + acc1h zeroing --------------------------
// Detect: 256 odd words sampled per block. int64 indices < 100000 have zero high
// words; int32 data puts edge values there (P(all 256 == 0) astronomically small).
#define DEG_ZT (N_NODES * HMW / 8)      // acc1h uint4s (8 halves each) = 400000
__global__ void k_deg(const void* ei) {
    __shared__ unsigned s_or[256];
    int t = threadIdx.x;
    s_or[t] = ((const unsigned*)ei)[2 * t + 1];
    __syncthreads();
    for (int s = 128; s > 0; s >>= 1) {
        if (t < s) s_or[t] |= s_or[t + s];
        __syncthreads();
    }
    int is64 = (s_or[0] == 0u) ? 1 : 0;
    if (blockIdx.x == 0 && t == 0) g_is64 = is64;

    int tid = blockIdx.x * 256 + t;
    if (tid < N_EDGES) {
        if (is64) {
            const long long* p = (const long long*)ei;
            int src = (int)p[tid];
            int dst = (int)p[N_EDGES + tid];
            g_src32[tid] = src;
            g_dst32[tid] = dst;
            atomicAdd(&g_deg[dst], 1.0f);
        } else {
            atomicAdd(&g_deg[((const int*)ei)[N_EDGES + tid]], 1.0f);
        }
    } else {
        int z = tid - N_EDGES;          // zero fp16 accumulator for this launch
        if (z < DEG_ZT) ((uint4*)g_acc1h)[z] = make_uint4(0u, 0u, 0u, 0u);
    }
}

__device__ __forceinline__ void load_edge(const void* ei, int is64, int e,
                                          int& src, int& dst) {
    if (is64) { src = g_src32[e]; dst = g_dst32[e]; }
    else {
        const int* p = (const int*)ei;
        src = p[e];
        dst = p[N_EDGES + e];
    }
}

// ---------------- layer-1 scatter: acc0[dst] += dis[src] * x[src]  (2 feats) ----
__global__ void k_scatter0(const void* ei, const float* __restrict__ x) {
    int e = blockIdx.x * 256 + threadIdx.x;
    if (e >= N_EDGES) return;
    int src, dst;
    load_edge(ei, g_is64, e, src, dst);
    float ds = rsqrtf(1.0f + g_deg[src]);
    float2 xv = ((const float2*)x)[src];
    red_add_v2(&g_acc0[2 * dst], ds * xv.x, ds * xv.y);
}

// ---------------- dense: h = relu(aggX @ W1 + b1); g = dis * (h @ [Wmu|Wls]) ----
// 4 threads/node (8 outputs each) x 4 nodes/thread (R6/R8-proven shape).
// Writes gvec fp16 (gather/REDG payload), exact f32 self term to g_gself, and
// part-0 lanes persist g_dis for the epilogue.
__global__ void __launch_bounds__(256) k_hidden(
        const float* __restrict__ x, const float* __restrict__ W1,
        const float* __restrict__ b1,
        const float* __restrict__ Wmu, const float* __restrict__ Wls) {
    __shared__ float4 sW4[64][8];   // [k][j/4] of concatenated [Wmu|Wls]
    __shared__ float4 sWb[64];      // (W1[0][k], W1[1][k], b1[k], 0)

    int t = threadIdx.x;
    for (int i = t; i < 512; i += 256) {
        int k = i >> 3, q = i & 7;
        sW4[k][q] = (q < 4) ? ((const float4*)Wmu)[k * 4 + q]
                            : ((const float4*)Wls)[k * 4 + (q - 4)];
    }
    if (t < 64) sWb[t] = make_float4(W1[t], W1[64 + t], b1[t], 0.0f);
    __syncthreads();

    int part = t & 3;               // which 8 of the 32 outputs
    int u    = t >> 2;              // 0..63
    int base = blockIdx.x * 256;

    float a0[4], a1[4], dd[4];
    #pragma unroll
    for (int i = 0; i < 4; i++) {
        int n = base + u + 64 * i;
        int nc = (n < N_NODES) ? n : 0;
        float d = rsqrtf(1.0f + g_deg[nc]);
        float2 xv = ((const float2*)x)[nc];
        float2 av = ((const float2*)g_acc0)[nc];
        a0[i] = d * av.x + d * d * xv.x;
        a1[i] = d * av.y + d * d * xv.y;
        dd[i] = d;
    }

    float acc[4][8];
    #pragma unroll
    for (int i = 0; i < 4; i++)
        #pragma unroll
        for (int j = 0; j < 8; j++) acc[i][j] = 0.0f;

    int q0 = part * 2;
    #pragma unroll 4
    for (int k = 0; k < 64; k++) {
        float4 wb = sWb[k];
        float4 wA = sW4[k][q0];
        float4 wB = sW4[k][q0 + 1];
        #pragma unroll
        for (int i = 0; i < 4; i++) {
            float hk = fmaxf(0.0f, fmaf(a0[i], wb.x, fmaf(a1[i], wb.y, wb.z)));
            acc[i][0] = fmaf(hk, wA.x, acc[i][0]);
            acc[i][1] = fmaf(hk, wA.y, acc[i][1]);
            acc[i][2] = fmaf(hk, wA.z, acc[i][2]);
            acc[i][3] = fmaf(hk, wA.w, acc[i][3]);
            acc[i][4] = fmaf(hk, wB.x, acc[i][4]);
            acc[i][5] = fmaf(hk, wB.y, acc[i][5]);
            acc[i][6] = fmaf(hk, wB.z, acc[i][6]);
            acc[i][7] = fmaf(hk, wB.w, acc[i][7]);
        }
    }

    #pragma unroll
    for (int i = 0; i < 4; i++) {
        int n = base + u + 64 * i;
        if (n < N_NODES) {
            float4 vA = make_float4(dd[i] * acc[i][0], dd[i] * acc[i][1],
                                    dd[i] * acc[i][2], dd[i] * acc[i][3]);
            float4 vB = make_float4(dd[i] * acc[i][4], dd[i] * acc[i][5],
                                    dd[i] * acc[i][6], dd[i] * acc[i][7]);
            float4* sout = (float4*)(g_gself + n * HMW + part * 8);
            sout[0] = vA;                  // exact f32 self-loop term
            sout[1] = vB;
            __half2 h0 = __float22half2_rn(make_float2(vA.x, vA.y));
            __half2 h1 = __float22half2_rn(make_float2(vA.z, vA.w));
            __half2 h2 = __float22half2_rn(make_float2(vB.x, vB.y));
            __half2 h3 = __float22half2_rn(make_float2(vB.z, vB.w));
            uint4 pk;
            pk.x = *(unsigned*)&h0; pk.y = *(unsigned*)&h1;
            pk.z = *(unsigned*)&h2; pk.w = *(unsigned*)&h3;
            *(uint4*)(g_gvech + n * HMW + part * 8) = pk;
            if (part == 0) g_dis[n] = dd[i];   // persist for epilogue
        }
    }
}

// ---------------- layer-2 scatter (fp16 packed REDG) + accumulator re-zeroing ----
// Edge range: 4 threads/edge; each gathers one uint4 (8 halves of gvech[src])
// and fires ONE red.v4.f16x2 (8 halves/lane) -> 6.4M REDG lanes (was 12.8M).
// Tail range: zero deg + acc0 for the NEXT launch.
#define S1_EDGE_T (N_EDGES * 4)
#define S1_ZD     (N_NODES / 4)          // deg float4s   (25000)
#define S1_ZA     (N_NODES * 2 / 4)      // acc0 float4s  (50000)
#define S1_TOTAL  (S1_EDGE_T + S1_ZD + S1_ZA)
__global__ void k_scatter1(const void* ei) {
    int tid = blockIdx.x * 256 + threadIdx.x;
    if (tid < S1_EDGE_T) {
        int e = tid >> 2, q = tid & 3;
        int src, dst;
        load_edge(ei, g_is64, e, src, dst);
        uint4 w = ((const uint4*)g_gvech)[src * 4 + q];     // 8 halves
        red_add_v4h2(g_acc1h + dst * HMW + q * 8, w);
    } else {
        int z = tid - S1_EDGE_T;
        const float4 zero = make_float4(0.f, 0.f, 0.f, 0.f);
        if (z < S1_ZD)                ((float4*)g_deg )[z] = zero;
        else if (z < S1_ZD + S1_ZA)   ((float4*)g_acc0)[z - S1_ZD] = zero;
    }
}

// ---------------- epilogue: out = dis*(acc1h + gself) + bias --------------------
__global__ void k_out(const float* __restrict__ bmu, const float* __restrict__ bls,
                      float* __restrict__ out) {
    int tid = blockIdx.x * 256 + threadIdx.x;       // over N_NODES * 8 quads
    if (tid >= N_NODES * 8) return;
    int n = tid >> 3, q = tid & 7;
    float d = g_dis[n];
    uint2 hw = ((const uint2*)g_acc1h)[tid];        // 4 halves (neighbor sum)
    float2 f0 = __half22float2(*(__half2*)&hw.x);
    float2 f1 = __half22float2(*(__half2*)&hw.y);
    float4 s = ((const float4*)g_gself)[tid];       // exact self term
    float4 b = (q < 4) ? ((const float4*)bmu)[q] : ((const float4*)bls)[q - 4];
    float4 v = make_float4(fmaf(d, f0.x + s.x, b.x), fmaf(d, f0.y + s.y, b.y),
                           fmaf(d, f1.x + s.z, b.z), fmaf(d, f1.y + s.w, b.w));
    float* dst = (q < 4) ? out + n * OUTC + q * 4
                         : out + N_NODES * OUTC + n * OUTC + (q - 4) * 4;
    *(float4*)dst = v;
}

extern "C" void kernel_launch(void* const* d_in, const int* in_sizes, int n_in,
                              void* d_out, int out_size) {
    const float* x    = (const float*)d_in[0];
    const void*  ei   = d_in[1];                 // int32 or int64, detected on device
    const float* W1   = (const float*)d_in[2];
    const float* b1   = (const float*)d_in[3];
    const float* Wmu  = (const float*)d_in[4];
    const float* bmu  = (const float*)d_in[5];
    const float* Wls  = (const float*)d_in[6];
    const float* bls  = (const float*)d_in[7];
    float* out = (float*)d_out;

    const int DB  = (N_EDGES + DEG_ZT + 255) / 256;       // 7813 (edges + acc1h zero)
    const int EB  = (N_EDGES + 255) / 256;                // 6250
    const int HB  = (N_NODES + 255) / 256;                // 391
    const int OB  = (N_NODES * 8 + 255) / 256;            // 3125
    const int S1B = (S1_TOTAL + 255) / 256;               // 25293

    k_deg<<<DB, 256>>>(ei);
    k_scatter0<<<EB, 256>>>(ei, x);
    k_hidden<<<HB, 256>>>(x, W1, b1, Wmu, Wls);
    k_scatter1<<<S1B, 256>>>(ei);
    k_out<<<OB, 256>>>(bmu, bls, out);
}